// round 17
// baseline (speedup 1.0000x reference)
#include <cuda_runtime.h>
#include <cuda_bf16.h>
#include <cstdint>
#include <math.h>

// Problem dims
#define BB 1024
#define DD 512
#define HH 1024
#define TT 64

#define NT 256            // 8 warps per CTA
#define GROUPS 8          // B/128 row groups
#define JPG 16            // CTAs per group (n-slices)
#define NCTA (GROUPS*JPG) // 128 CTAs -> 1 per SM

// ---------------- persistent state (all fragment-major, no SMEM residency) ----------------
__device__ float g_y[BB*DD];
__device__ float g_ks[BB*DD];
// A-operand fragments: [grp][kc][mtile(8)][512B]
__device__ char  g_xf[GROUPS*131072];   // 1MB  (32 kc)
__device__ char  g_hf[GROUPS*262144];   // 2MB  (64 kc)
// B-operand fragments: [jslice][kc][pair][512B]
__device__ char  g_W1F[1048576];        // 16 x (32 kc x 4 pairs x 512B)
__device__ char  g_W2F[1048576];        // 16 x (64 kc x 2 pairs x 512B)
__device__ unsigned g_barrier[GROUPS*32 + 32];

// ---------------- helpers ----------------
// A fragments: mutable cross-CTA data -> L2-coherent (.cg)
__device__ __forceinline__ void ldg_cg(uint32_t* a, const char* p) {
    asm volatile("ld.global.cg.v4.u32 {%0,%1,%2,%3}, [%4];"
                 : "=r"(a[0]), "=r"(a[1]), "=r"(a[2]), "=r"(a[3]) : "l"(p));
}
// B fragments: immutable weights -> L1-cached (.nc)
__device__ __forceinline__ void ldg_nc(uint32_t* a, const char* p) {
    asm volatile("ld.global.nc.v4.u32 {%0,%1,%2,%3}, [%4];"
                 : "=r"(a[0]), "=r"(a[1]), "=r"(a[2]), "=r"(a[3]) : "l"(p));
}
__device__ __forceinline__ void stg_v2(char* p, uint32_t v0, uint32_t v1) {
    asm volatile("st.global.v2.u32 [%0], {%1,%2};" :: "l"(p), "r"(v0), "r"(v1) : "memory");
}
__device__ __forceinline__ void mma16816(float* c, const uint32_t* a, uint32_t b0, uint32_t b1) {
    asm volatile("mma.sync.aligned.m16n8k16.row.col.f32.bf16.bf16.f32 "
                 "{%0,%1,%2,%3}, {%4,%5,%6,%7}, {%8,%9}, {%0,%1,%2,%3};"
                 : "+f"(c[0]), "+f"(c[1]), "+f"(c[2]), "+f"(c[3])
                 : "r"(a[0]), "r"(a[1]), "r"(a[2]), "r"(a[3]), "r"(b0), "r"(b1));
}

// fast tanh via MUFU ex2/rcp
__device__ __forceinline__ float fast_tanh(float x) {
    float ax = fabsf(x);
    float e, r;
    asm("ex2.approx.f32 %0, %1;" : "=f"(e) : "f"(ax * 2.8853900817779268f));
    asm("rcp.approx.f32 %0, %1;" : "=f"(r) : "f"(e + 1.0f));
    float t = fmaf(-2.0f, r, 1.0f);
    return copysignf(t, x);
}
__device__ __forceinline__ uint32_t bf2u(float a, float b) {
    __nv_bfloat162 t = __floats2bfloat162_rn(a, b);
    return *reinterpret_cast<uint32_t*>(&t);
}

// lightweight cross-CTA barrier
__device__ __forceinline__ void group_bar(unsigned* cnt, unsigned target) {
    __syncthreads();
    if (threadIdx.x == 0) {
        __threadfence();
        atomicAdd(cnt, 1u);
        while (*(volatile unsigned*)cnt < target) { __nanosleep(32); }
        __threadfence();
    }
    __syncthreads();
}

__global__ void ode_reset() {
    if (threadIdx.x < GROUPS * 32 + 32) g_barrier[threadIdx.x] = 0u;
}

// A-fragment byte offset within a group image (8 mtiles per kc)
__device__ __forceinline__ uint32_t afrag_off(int ml, int k) {
    return (uint32_t)(((k >> 4) * 8 + (ml >> 4)) * 512
         + ((ml & 7) * 4 + ((k & 7) >> 1)) * 16
         + (((ml >> 3) & 1) + 2 * ((k >> 3) & 1)) * 4
         + (k & 1) * 2);
}
// B-fragment byte offset within a slice image (npairs pairs per kc); k-bit masked (R14 fix)
__device__ __forceinline__ uint32_t bfrag_off(int npairs, int n, int k) {
    int pair = n >> 4, t = (n >> 3) & 1, nn = n & 7;
    int u = (k >> 3) & 1;
    int l = nn * 4 + ((k & 7) >> 1);
    return (uint32_t)(((k >> 4) * npairs + pair) * 512 + l * 16 + (u * 2 + t) * 4 + (k & 1) * 2);
}

// ---------------- persistent fused RK4 solver ----------------
__global__ void __launch_bounds__(NT)
ode_persistent(const float* __restrict__ first,
               const float* __restrict__ W1, const float* __restrict__ b1,
               const float* __restrict__ W2, const float* __restrict__ b2,
               const float* __restrict__ ts, float* __restrict__ out)
{
    __shared__ float red[4][32][32];    // [wM][acc idx][lane] K-split reduction (16KB)

    const int tid  = threadIdx.x;
    const int wid  = tid >> 5, lane = tid & 31;
    const int wM   = wid & 3;          // 4 warps along M (32 rows each)
    const int wHi  = wid >> 2;         // GEMM1: N-half; GEMM2: K-half

    const int grp  = blockIdx.y;       // 0..7
    const int j    = blockIdx.x;       // 0..15
    const int cta  = grp * JPG + j;
    const int m0   = grp * 128;
    const int n1_0 = j * 64;
    const int n2_0 = j * 32;
    unsigned* cnt  = &g_barrier[grp * 32];

    // ============ init phase (partitioned across 128 CTAs) ============
    {
        const int base_i = cta * 4096;
        for (int t = tid; t < 4096; t += NT) {
            const int i = base_i + t;
            {   // W1 [D][H] -> B-fragment slices (k = d, n = h), 16 slices of N64
                int d = i / HH, h = i % HH;
                int jj = h >> 6, n = h & 63;
                uint32_t off = (uint32_t)(jj * 65536) + bfrag_off(4, n, d);
                *(__nv_bfloat16*)(g_W1F + off) = __float2bfloat16(W1[i]);
            }
            {   // W2 [H][D] -> B-fragment slices (k = h, n = d), 16 slices of N32
                int h = i / DD, d = i % DD;
                int jj = d >> 5, n = d & 31;
                uint32_t off = (uint32_t)(jj * 65536) + bfrag_off(2, n, h);
                *(__nv_bfloat16*)(g_W2F + off) = __float2bfloat16(W2[i]);
            }
            {   // state init: y, out, x fragments (grp = 128-row block)
                float v = first[i];
                g_y[i] = v;
                out[i] = v;
                int m = i / DD, d = i % DD;
                int gg = m >> 7, ml = m & 127;
                uint32_t off = (uint32_t)(gg * 131072) + afrag_off(ml, d);
                *(__nv_bfloat16*)(g_xf + off) = __float2bfloat16(v);
            }
        }
    }
    group_bar(&g_barrier[GROUPS * 32], NCTA);   // weights + x(0) visible

    const char* xg  = g_xf + grp * 131072;
    char*       hgw = g_hf + grp * 262144;
    const char* hg  = hgw;
    char*       xgw = g_xf + grp * 131072;
    const char* w1f = g_W1F + j * 65536;
    const char* w2f = g_W2F + j * 65536;

    const int rl = lane >> 2;
    const int cl = (lane & 3) * 2;
    const int lp = rl * 4 + (lane & 3);
    unsigned tgt = 0;

    for (int s = 0; s < (TT - 1) * 4; ++s) {
        const int step  = s >> 2;
        const int stage = (s & 3) + 1;

        // ================= GEMM1: h = tanh(x @ W1 + b1) =================
        // warp grid 4M x 2N, warp tile M32 x N32, serial kc 0..31
        tgt += JPG;
        group_bar(cnt, tgt);

        float acc[2][4][4];
        #pragma unroll
        for (int a = 0; a < 2; ++a)
            #pragma unroll
            for (int b = 0; b < 4; ++b)
                #pragma unroll
                for (int q = 0; q < 4; ++q) acc[a][b][q] = 0.f;

        #pragma unroll 4
        for (int kc = 0; kc < 32; ++kc) {
            uint32_t af[2][4], bf[2][4];
            #pragma unroll
            for (int mi = 0; mi < 2; ++mi)
                ldg_cg(af[mi], xg + (size_t)((kc * 8 + 2 * wM + mi) * 512) + lane * 16);
            #pragma unroll
            for (int pp = 0; pp < 2; ++pp)
                ldg_nc(bf[pp], w1f + (size_t)((kc * 4 + 2 * wHi + pp) * 512) + lane * 16);
            #pragma unroll
            for (int mi = 0; mi < 2; ++mi)
                #pragma unroll
                for (int pp = 0; pp < 2; ++pp) {
                    mma16816(acc[mi][2 * pp],     af[mi], bf[pp][0], bf[pp][2]);
                    mma16816(acc[mi][2 * pp + 1], af[mi], bf[pp][1], bf[pp][3]);
                }
        }

        // tanh epilogue -> h fragments, cols [n1_0 + wHi*32, +32)
        #pragma unroll
        for (int mi = 0; mi < 2; ++mi) {
            const int mt = 2 * wM + mi;
            #pragma unroll
            for (int ni = 0; ni < 4; ++ni) {
                const int n = n1_0 + wHi * 32 + ni * 8 + cl;
                const float bb0 = b1[n], bb1 = b1[n + 1];
                uint32_t v0 = bf2u(fast_tanh(acc[mi][ni][0] + bb0), fast_tanh(acc[mi][ni][1] + bb1));
                uint32_t v1 = bf2u(fast_tanh(acc[mi][ni][2] + bb0), fast_tanh(acc[mi][ni][3] + bb1));
                char* p = hgw + (size_t)(((n >> 4) * 8 + mt) * 512) + lp * 16 + ((n >> 3) & 1) * 8;
                stg_v2(p, v0, v1);
            }
        }

        // ================= GEMM2: k = h @ W2 + b2 ; RK4 update =================
        // warp grid 4M x 2K, warp tile M32 x N32 x K512-half
        tgt += JPG;
        group_bar(cnt, tgt);

        float ac2[2][4][4];
        #pragma unroll
        for (int a = 0; a < 2; ++a)
            #pragma unroll
            for (int b = 0; b < 4; ++b)
                #pragma unroll
                for (int q = 0; q < 4; ++q) ac2[a][b][q] = 0.f;

        #pragma unroll 4
        for (int kk = 0; kk < 32; ++kk) {
            const int kc = wHi * 32 + kk;
            uint32_t af[2][4], bf[2][4];
            #pragma unroll
            for (int mi = 0; mi < 2; ++mi)
                ldg_cg(af[mi], hg + (size_t)((kc * 8 + 2 * wM + mi) * 512) + lane * 16);
            #pragma unroll
            for (int pp = 0; pp < 2; ++pp)
                ldg_nc(bf[pp], w2f + (size_t)((kc * 2 + pp) * 512) + lane * 16);
            #pragma unroll
            for (int mi = 0; mi < 2; ++mi)
                #pragma unroll
                for (int pp = 0; pp < 2; ++pp) {
                    mma16816(ac2[mi][2 * pp],     af[mi], bf[pp][0], bf[pp][2]);
                    mma16816(ac2[mi][2 * pp + 1], af[mi], bf[pp][1], bf[pp][3]);
                }
        }

        // K-half reduction through smem
        if (wHi == 1) {
            #pragma unroll
            for (int mi = 0; mi < 2; ++mi)
                #pragma unroll
                for (int b = 0; b < 4; ++b)
                    #pragma unroll
                    for (int q = 0; q < 4; ++q)
                        red[wM][mi * 16 + b * 4 + q][lane] = ac2[mi][b][q];
        }
        __syncthreads();
        if (wHi == 0) {
            #pragma unroll
            for (int mi = 0; mi < 2; ++mi)
                #pragma unroll
                for (int b = 0; b < 4; ++b)
                    #pragma unroll
                    for (int q = 0; q < 4; ++q)
                        ac2[mi][b][q] += red[wM][mi * 16 + b * 4 + q][lane];

            // RK4 epilogue (wHi==0 warps; tile M128 x N32)
            const float dt = ts[step + 1] - ts[step];
            #pragma unroll
            for (int mi = 0; mi < 2; ++mi) {
                const int mt = 2 * wM + mi;
                #pragma unroll
                for (int ni = 0; ni < 4; ++ni) {
                    const int n = n2_0 + ni * 8 + cl;
                    const float bb0 = b2[n], bb1 = b2[n + 1];
                    uint32_t xv[2];
                    #pragma unroll
                    for (int hh = 0; hh < 2; ++hh) {
                        const int m = m0 + wM * 32 + mi * 16 + rl + hh * 8;
                        const size_t off = (size_t)m * DD + n;
                        float kq0 = ac2[mi][ni][2 * hh]     + bb0;
                        float kq1 = ac2[mi][ni][2 * hh + 1] + bb1;
                        float2 y2 = *(const float2*)(g_y + off);
                        float ks0 = 0.f, ks1 = 0.f;
                        if (stage >= 2) {
                            float2 t = *(const float2*)(g_ks + off);
                            ks0 = t.x; ks1 = t.y;
                        }
                        float x0, x1;
                        if (stage == 4) {
                            const float w = dt * (1.0f / 6.0f);
                            x0 = y2.x + w * (ks0 + kq0);
                            x1 = y2.y + w * (ks1 + kq1);
                            *(float2*)(g_y + off) = make_float2(x0, x1);
                            *(float2*)(out + (size_t)(step + 1) * (BB * DD) + off) = make_float2(x0, x1);
                        } else {
                            const float cf = (stage == 3) ? dt : 0.5f * dt;
                            const float wk = (stage == 1) ? 1.0f : 2.0f;
                            *(float2*)(g_ks + off) = make_float2(ks0 + wk * kq0, ks1 + wk * kq1);
                            x0 = y2.x + cf * kq0;
                            x1 = y2.y + cf * kq1;
                        }
                        xv[hh] = bf2u(x0, x1);
                    }
                    char* p = xgw + (size_t)(((n >> 4) * 8 + mt) * 512) + lp * 16 + ((n >> 3) & 1) * 8;
                    stg_v2(p, xv[0], xv[1]);
                }
            }
        }
        // next iteration's group_bar supplies the closing sync + release
    }
}

// ---------------- launch ----------------
extern "C" void kernel_launch(void* const* d_in, const int* in_sizes, int n_in,
                              void* d_out, int out_size)
{
    const float* first = (const float*)d_in[0];
    const float* ts    = (const float*)d_in[1];
    const float* W1    = (const float*)d_in[2];
    const float* b1    = (const float*)d_in[3];
    const float* W2    = (const float*)d_in[4];
    const float* b2    = (const float*)d_in[5];
    float* out = (float*)d_out;

    ode_reset<<<1, 288>>>();
    ode_persistent<<<dim3(JPG, GROUPS), NT>>>(first, W1, b1, W2, b2, ts, out);
}